// round 15
// baseline (speedup 1.0000x reference)
#include <cuda_runtime.h>

// PCEN, single fused kernel: x read ONCE, cached in SHARED MEMORY.
//
//   M[t] = a*M[t-1] + s*x[t],  a = 0.975, s = 0.025,  M[0] = x[0]
//   out  = sqrt(x * (M+eps)^(-alpha) + delta) - sqrt(delta)
//
// x: (B=64, T=4000, F=128) fp32. CHUNK=20 rows, NCHUNK=200. Block = 8 warps
// = 8 consecutive chunks of one batch; 1600 blocks, 96 KB dynamic smem
// (80 KB x tile + 16 KB partial window) -> 2 blocks/SM, 16 warps/SM, ~56 regs
// (R14's failure was the 80-reg x cache spilling at regs=168).
//
// Per block:
//  A: each warp streams its 20 rows into the smem tile while accumulating the
//     zero-state chunk partial (chunk 0 carries the true seed M[0]=x[0]).
//     Partials -> window smem + g_local; publish flag (fence->sync->flag).
//  B: flat wait on <=3 same-batch predecessor blocks' flags (partials are
//     purely local: no cross-block value chain), stage their 24 partials.
//  C: per-warp checkpoint via truncated Horner over KT=24 partials
//     (a^(20*24) ~= 5e-6 -> output error ~2e-6; exact combine near t=0).
//  D: sweep the smem tile, write output with evict-first stores.
// Deadlock-free: waits target lower block IDs only; CWD dispatches in order;
// publishing precedes waiting in every block.

#define B_LEN   64
#define T_LEN   4000
#define F4      32                 // 128 floats = 32 float4 lanes
#define CHUNK   20
#define NCHUNK  200                // T_LEN / CHUNK
#define WPB     8                  // warps (= chunks) per block
#define BLKB    (NCHUNK / WPB)     // 25 blocks per batch
#define NBLK    (B_LEN * BLKB)     // 1600
#define KT      24                 // truncation window (chunks), 3 blocks
#define NWIN    (KT + WPB)         // 32 window slots
#define TILE_F4 (WPB * CHUNK * F4) // 5120 float4 = 80 KB
#define SMEM_BYTES ((TILE_F4 + NWIN * F4) * (int)sizeof(float4))  // 96 KB

#define C_S       0.025f
#define C_A       0.975f
#define C_EPS     1e-6f
#define C_NALPHA (-0.98f)
#define C_DELTA   2.0f
#define C_SQRTD   1.41421356237309515f

__device__ float4 g_local[B_LEN * NCHUNK * F4];   // chunk partials, 6.5 MB
__device__ int    g_flag[NBLK];

__device__ __forceinline__ float f_lg2(float v) {
    float r; asm("lg2.approx.f32 %0, %1;" : "=f"(r) : "f"(v)); return r;
}
__device__ __forceinline__ float f_ex2(float v) {
    float r; asm("ex2.approx.f32 %0, %1;" : "=f"(r) : "f"(v)); return r;
}
__device__ __forceinline__ float f_sqrt(float v) {
    float r; asm("sqrt.approx.f32 %0, %1;" : "=f"(r) : "f"(v)); return r;
}
__device__ __forceinline__ float pcen1(float xv, float mv) {
    return f_sqrt(fmaf(xv, f_ex2(C_NALPHA * f_lg2(mv + C_EPS)), C_DELTA)) - C_SQRTD;
}
__device__ __forceinline__ float4 ema4(float4 m, float4 xv) {
    m.x = fmaf(C_A, m.x, C_S * xv.x);
    m.y = fmaf(C_A, m.y, C_S * xv.y);
    m.z = fmaf(C_A, m.z, C_S * xv.z);
    m.w = fmaf(C_A, m.w, C_S * xv.w);
    return m;
}
__device__ __forceinline__ float4 comb4(float aL, float4 I, float4 P) {
    float4 r;
    r.x = fmaf(aL, I.x, P.x);
    r.y = fmaf(aL, I.y, P.y);
    r.z = fmaf(aL, I.z, P.z);
    r.w = fmaf(aL, I.w, P.w);
    return r;
}
__device__ __forceinline__ float a_pow_chunk() {   // a^CHUNK, constant-folded
    double ad = 1.0;
    #pragma unroll
    for (int i = 0; i < CHUNK; ++i) ad *= 0.975;
    return (float)ad;
}

__global__ void pcen_init_flags() {
    int i = blockIdx.x * blockDim.x + threadIdx.x;
    if (i < NBLK) g_flag[i] = 0;
}

__global__ void __launch_bounds__(256)
pcen_fused(const float4* __restrict__ x4, float4* __restrict__ out4) {
    extern __shared__ float4 smem[];
    float4* tile = smem;                 // [WPB*CHUNK][F4] x cache
    float4* sp   = smem + TILE_F4;       // [NWIN][F4] partial window

    const int bid = blockIdx.x;
    const int b   = bid / BLKB;
    const int cb  = bid - b * BLKB;
    const int c0  = cb * WPB;
    const int w   = threadIdx.x >> 5;
    const int l   = threadIdx.x & 31;
    const int c   = c0 + w;                          // this warp's chunk

    const int wlo   = (c0 > KT) ? (c0 - KT) : 0;     // window start chunk
    const int npred = (c0 - wlo) / WPB;              // predecessor blocks <=3

    // ---- Phase A: stream x -> smem tile + zero-state partial; publish ----
    const size_t base = (size_t)(b * T_LEN + c * CHUNK) * F4 + l;
    const float4* px = x4 + base;

    float4 m = make_float4(0.f, 0.f, 0.f, 0.f);
    {
        // chunk 0: pre-state x[0] makes the uniform update exact
        // (a*x0 + s*x0 == x0), so seed with row 0 before the sweep.
        const float4 x0 = px[0];
        if (c == 0) m = x0;
        #pragma unroll 5
        for (int i = 0; i < CHUNK; ++i) {
            const float4 xv = (i == 0) ? x0 : px[(size_t)i * F4];
            tile[(w * CHUNK + i) * F4 + l] = xv;
            m = ema4(m, xv);
        }
    }

    sp[(c - wlo) * F4 + l] = m;                        // own window slot
    g_local[(size_t)(b * NCHUNK + c) * F4 + l] = m;    // for successor blocks
    __threadfence();
    __syncthreads();
    if (threadIdx.x == 0) {
        *((volatile int*)&g_flag[bid]) = 1;
    }

    // ---- Phase B: flat wait on predecessors, stage their partials ----
    if (npred > 0) {
        if (threadIdx.x < npred) {
            volatile int* f = &g_flag[bid - npred + threadIdx.x];
            while (*f == 0) { }
            __threadfence();
        }
        __syncthreads();
        const float4* gw = &g_local[(size_t)(b * NCHUNK + wlo) * F4];
        for (int i = threadIdx.x; i < npred * WPB * F4; i += 256) {
            sp[i] = gw[i];
        }
        __syncthreads();
    }

    const float aL = a_pow_chunk();

    // ---- Phase C: checkpoint S(c-1) via Horner over the window ----
    if (c == 0) {
        m = tile[l];                               // exact pre-state x[0]
    } else if (wlo > 0) {
        // fixed KT terms: chunks c-KT .. c-1 -> slots w .. w+KT-1
        m = sp[w * F4 + l];
        #pragma unroll 4
        for (int j = w + 1; j < w + KT; ++j) {
            m = comb4(aL, m, sp[j * F4 + l]);
        }
    } else {
        // near the start: exact combine from chunk 0 (includes true seed)
        m = sp[l];
        for (int j = 1; j <= c - 1; ++j) {
            m = comb4(aL, m, sp[j * F4 + l]);
        }
    }

    // ---- Phase D: sweep smem tile, write output ----
    float4* po = out4 + base;
    #pragma unroll 5
    for (int i = 0; i < CHUNK; ++i) {
        const float4 xv = tile[(w * CHUNK + i) * F4 + l];
        m = ema4(m, xv);
        float4 o;
        o.x = pcen1(xv.x, m.x);
        o.y = pcen1(xv.y, m.y);
        o.z = pcen1(xv.z, m.z);
        o.w = pcen1(xv.w, m.w);
        __stcs(&po[(size_t)i * F4], o);
    }
}

extern "C" void kernel_launch(void* const* d_in, const int* in_sizes, int n_in,
                              void* d_out, int out_size) {
    const float4* x4 = (const float4*)d_in[0];
    float4* out4 = (float4*)d_out;
    (void)in_sizes; (void)n_in; (void)out_size;

    // Idempotent, deterministic; first (pre-capture) call sets it for good.
    cudaFuncSetAttribute(pcen_fused,
                         cudaFuncAttributeMaxDynamicSharedMemorySize,
                         SMEM_BYTES);

    pcen_init_flags<<<(NBLK + 255) / 256, 256>>>();
    pcen_fused<<<NBLK, 256, SMEM_BYTES>>>(x4, out4);
}

// round 16
// speedup vs baseline: 1.2853x; 1.2853x over previous
#include <cuda_runtime.h>

// PCEN, fused single main pass: x re-read served from L2 (no in-block cache).
//
//   M[t] = a*M[t-1] + s*x[t],  a = 0.975, s = 0.025,  M[0] = x[0]
//   out  = sqrt(x * (M+eps)^(-alpha) + delta) - sqrt(delta)
//
// x: (B=64, T=4000, F=128) fp32. CHUNK=25, NCHUNK=160. Block = 4 warps =
// 4 consecutive chunks of one batch; 2560 blocks x 128 thr, ~10 KB smem ->
// 16 blocks/SM (R14 failed on reg spill, R15 on smem-capped occupancy; here
// the x slice is cached in L2 between the two sweeps: reuse distance ~2-3 us
// of chip streaming (~15 MB) << 126 MB L2).
//
// Per block:
//  A: each warp streams its 25 rows (DRAM -> L2), computes the zero-state
//     chunk partial (chunk 0 carries the true seed via the pre-state trick:
//     m0 = x[0] makes the uniform update exact since a+s = 1).
//     Partials -> own smem window slot + g_local; fence -> sync -> flag.
//  B: flat wait on <=4 same-batch predecessor blocks' flags (partials are
//     purely local; no cross-block value chain), stage KT=16 partials.
//  C: per-warp checkpoint via truncated Horner over KT partials
//     (a^(25*16) ~= 4e-5 -> output err ~2e-5, 40x under the 1e-3 gate;
//     exact combine for chunks <= KT).
//  D: re-sweep the same 25 rows (L2 hits), write output with __stcs.
// Deadlock-free: waits target strictly lower block IDs; CWD dispatches in
// order; publishing precedes waiting in every block.

#define B_LEN   64
#define T_LEN   4000
#define F4      32               // 128 floats = 32 float4 lanes
#define CHUNK   25
#define NCHUNK  160              // T_LEN / CHUNK
#define BLKB    (NCHUNK / 4)     // 40 blocks per batch
#define NBLK    (B_LEN * BLKB)   // 2560
#define KT      16               // truncation window (chunks) = 4 blocks
#define NWIN    (KT + 4)         // smem slots: chunks [c0-KT, c0+4)

#define C_S       0.025f
#define C_A       0.975f
#define C_EPS     1e-6f
#define C_NALPHA (-0.98f)
#define C_DELTA   2.0f
#define C_SQRTD   1.41421356237309515f

__device__ float4 g_local[B_LEN * NCHUNK * F4];   // chunk partials, 5.2 MB
__device__ int    g_flag[NBLK];

__device__ __forceinline__ float f_lg2(float v) {
    float r; asm("lg2.approx.f32 %0, %1;" : "=f"(r) : "f"(v)); return r;
}
__device__ __forceinline__ float f_ex2(float v) {
    float r; asm("ex2.approx.f32 %0, %1;" : "=f"(r) : "f"(v)); return r;
}
__device__ __forceinline__ float f_sqrt(float v) {
    float r; asm("sqrt.approx.f32 %0, %1;" : "=f"(r) : "f"(v)); return r;
}
__device__ __forceinline__ float pcen1(float xv, float mv) {
    return f_sqrt(fmaf(xv, f_ex2(C_NALPHA * f_lg2(mv + C_EPS)), C_DELTA)) - C_SQRTD;
}
__device__ __forceinline__ float4 ema4(float4 m, float4 xv) {
    m.x = fmaf(C_A, m.x, C_S * xv.x);
    m.y = fmaf(C_A, m.y, C_S * xv.y);
    m.z = fmaf(C_A, m.z, C_S * xv.z);
    m.w = fmaf(C_A, m.w, C_S * xv.w);
    return m;
}
__device__ __forceinline__ float4 comb4(float aL, float4 I, float4 P) {
    float4 r;
    r.x = fmaf(aL, I.x, P.x);
    r.y = fmaf(aL, I.y, P.y);
    r.z = fmaf(aL, I.z, P.z);
    r.w = fmaf(aL, I.w, P.w);
    return r;
}
__device__ __forceinline__ float a_pow_chunk() {   // a^CHUNK, constant-folded
    double ad = 1.0;
    #pragma unroll
    for (int i = 0; i < CHUNK; ++i) ad *= 0.975;
    return (float)ad;
}

__global__ void pcen_init_flags() {
    int i = blockIdx.x * blockDim.x + threadIdx.x;
    if (i < NBLK) g_flag[i] = 0;
}

__global__ void __launch_bounds__(128)
pcen_fused(const float4* __restrict__ x4, float4* __restrict__ out4) {
    __shared__ float4 sp[NWIN * F4];               // 10 KB partial window

    const int bid = blockIdx.x;
    const int b   = bid / BLKB;
    const int cb  = bid - b * BLKB;
    const int c0  = cb * 4;
    const int w   = threadIdx.x >> 5;
    const int l   = threadIdx.x & 31;
    const int c   = c0 + w;                        // this warp's chunk

    const int wlo   = (c0 > KT) ? (c0 - KT) : 0;   // window start chunk
    const int npred = (c0 - wlo) >> 2;             // predecessor blocks <= 4

    // ---- Phase A: first sweep (DRAM -> L2), zero-state partial, publish ----
    const size_t base = (size_t)(b * T_LEN + c * CHUNK) * F4 + l;
    const float4* px = x4 + base;

    const float4 x0 = px[0];
    // chunk 0: pre-state x[0] makes the uniform update exact (a+s == 1).
    float4 m = (c == 0) ? x0 : make_float4(0.f, 0.f, 0.f, 0.f);
    #pragma unroll 5
    for (int i = 0; i < CHUNK; ++i) {
        const float4 xv = (i == 0) ? x0 : px[(size_t)i * F4];
        m = ema4(m, xv);
    }

    sp[(c - wlo) * F4 + l] = m;                        // own window slot
    g_local[(size_t)(b * NCHUNK + c) * F4 + l] = m;    // for successor blocks
    __threadfence();
    __syncthreads();
    if (threadIdx.x == 0) {
        *((volatile int*)&g_flag[bid]) = 1;
    }

    // ---- Phase B: flat wait on predecessors, stage their partials ----
    if (npred > 0) {
        if (threadIdx.x < npred) {
            volatile int* f = &g_flag[bid - npred + threadIdx.x];
            while (*f == 0) { }
            __threadfence();
        }
        __syncthreads();
        const float4* gw = &g_local[(size_t)(b * NCHUNK + wlo) * F4];
        for (int i = threadIdx.x; i < npred * 4 * F4; i += 128) {
            sp[i] = gw[i];
        }
        __syncthreads();
    }

    const float aL = a_pow_chunk();

    // ---- Phase C: checkpoint S(c-1) via Horner over the window ----
    if (c == 0) {
        m = x0;                                    // exact pre-state
    } else if (wlo > 0) {
        // fixed KT terms: chunks c-KT .. c-1 -> slots w .. w+KT-1
        m = sp[w * F4 + l];
        #pragma unroll 5
        for (int j = w + 1; j < w + KT; ++j) {
            m = comb4(aL, m, sp[j * F4 + l]);
        }
    } else {
        // near the start: exact combine from chunk 0 (includes true seed)
        m = sp[l];
        for (int j = 1; j <= c - 1; ++j) {
            m = comb4(aL, m, sp[j * F4 + l]);
        }
    }

    // ---- Phase D: second sweep (L2 hits), write output ----
    float4* po = out4 + base;
    #pragma unroll 5
    for (int i = 0; i < CHUNK; ++i) {
        const float4 xv = (i == 0) ? x0 : px[(size_t)i * F4];
        m = ema4(m, xv);
        float4 o;
        o.x = pcen1(xv.x, m.x);
        o.y = pcen1(xv.y, m.y);
        o.z = pcen1(xv.z, m.z);
        o.w = pcen1(xv.w, m.w);
        __stcs(&po[(size_t)i * F4], o);   // evict-first: keep L2 for x
    }
}

extern "C" void kernel_launch(void* const* d_in, const int* in_sizes, int n_in,
                              void* d_out, int out_size) {
    const float4* x4 = (const float4*)d_in[0];
    float4* out4 = (float4*)d_out;
    (void)in_sizes; (void)n_in; (void)out_size;

    pcen_init_flags<<<(NBLK + 255) / 256, 256>>>();
    pcen_fused<<<NBLK, 128>>>(x4, out4);
}

// round 17
// speedup vs baseline: 1.4448x; 1.1241x over previous
#include <cuda_runtime.h>

// PCEN via linear-recurrence chunk decomposition, two streaming passes.
//
//   M[t] = a*M[t-1] + s*x[t],  a = 0.975, s = 0.025,  M[0] = x[0]
//   out  = sqrt(x * (M+eps)^(-alpha) + delta) - sqrt(delta)
//
// x: (B=64, T=4000, F=128) fp32, CHUNK=25, NCHUNK=160.
//  P1: warp owns TWO adjacent 25-row chunks (50 contiguous rows) and runs two
//      independent zero-state EMA chains interleaved -> ~10 LDG.128 in flight
//      per thread (R12's single-chain unroll-5 only sustained ~4.5 TB/s; R10's
//      50-row warps reached 5.0+). Emits both 25-row partials.
//      Chunk 0 carries the true seed via the pre-state trick (a+s == 1:
//      m = x[0] makes the uniform update produce M[0] = x[0] exactly).
//  P3: block = 4 consecutive chunks of one batch; stages the KT=16-chunk
//      partial window into smem, reconstructs each warp's checkpoint with a
//      truncated Horner chain (a^(25*16) ~= 4e-5 -> output err ~2e-5, 40x
//      under the 1e-3 gate; exact combine for chunks <= KT), then sweeps its
//      25 rows and writes output with evict-first stores.

#define B_LEN   64
#define T_LEN   4000
#define F4      32               // 128 floats = 32 float4 lanes
#define CHUNK   25
#define NCHUNK  160              // T_LEN / CHUNK
#define NPAIR   (B_LEN * NCHUNK) // 10240 (b,c) pairs
#define NDUO    (NPAIR / 2)      // 5120 chunk-pairs for P1
#define KT      16               // truncation window (chunks)
#define NWIN    (KT + 4)         // P3 smem slots: chunks [c0-KT .. c0+4)

#define C_S       0.025f
#define C_A       0.975f
#define C_EPS     1e-6f
#define C_NALPHA (-0.98f)
#define C_DELTA   2.0f
#define C_SQRTD   1.41421356237309515f

// Chunk-local zero-state partials, [b][c][lane]. 5.2 MB, L2-resident.
__device__ float4 g_local[NPAIR * F4];

__device__ __forceinline__ float f_lg2(float v) {
    float r; asm("lg2.approx.f32 %0, %1;" : "=f"(r) : "f"(v)); return r;
}
__device__ __forceinline__ float f_ex2(float v) {
    float r; asm("ex2.approx.f32 %0, %1;" : "=f"(r) : "f"(v)); return r;
}
__device__ __forceinline__ float f_sqrt(float v) {
    float r; asm("sqrt.approx.f32 %0, %1;" : "=f"(r) : "f"(v)); return r;
}
__device__ __forceinline__ float pcen1(float xv, float mv) {
    return f_sqrt(fmaf(xv, f_ex2(C_NALPHA * f_lg2(mv + C_EPS)), C_DELTA)) - C_SQRTD;
}
__device__ __forceinline__ float4 ema4(float4 m, float4 xv) {
    m.x = fmaf(C_A, m.x, C_S * xv.x);
    m.y = fmaf(C_A, m.y, C_S * xv.y);
    m.z = fmaf(C_A, m.z, C_S * xv.z);
    m.w = fmaf(C_A, m.w, C_S * xv.w);
    return m;
}
__device__ __forceinline__ float4 comb4(float aL, float4 I, float4 P) {
    float4 r;
    r.x = fmaf(aL, I.x, P.x);
    r.y = fmaf(aL, I.y, P.y);
    r.z = fmaf(aL, I.z, P.z);
    r.w = fmaf(aL, I.w, P.w);
    return r;
}
__device__ __forceinline__ float a_pow_chunk() {   // a^CHUNK, constant-folded
    double ad = 1.0;
    #pragma unroll
    for (int i = 0; i < CHUNK; ++i) ad *= 0.975;
    return (float)ad;
}

// ---- P1: dual-chain chunk partials ----
// grid: NDUO/4 = 1280 blocks x 128 threads; warp = 2 adjacent chunks (50 rows).
__global__ void __launch_bounds__(128)
pcen_local(const float4* __restrict__ x4) {
    const int u    = blockIdx.x * 4 + (threadIdx.x >> 5);   // duo id
    const int lane = threadIdx.x & 31;
    const int d    = u % (NCHUNK / 2);                      // duo within batch
    const int b    = u / (NCHUNK / 2);
    const int c    = d * 2;                                 // first chunk

    const float4* px = x4 + (size_t)(b * T_LEN + c * CHUNK) * F4 + lane;

    // Chain A = chunk c (rows 0..24), chain B = chunk c+1 (rows 25..49).
    const float4 x0 = px[0];
    // c==0: pre-state x[0] makes the uniform update exact (a+s == 1).
    float4 ma = (c == 0) ? x0 : make_float4(0.f, 0.f, 0.f, 0.f);
    float4 mb = make_float4(0.f, 0.f, 0.f, 0.f);

    #pragma unroll 5
    for (int i = 0; i < CHUNK; ++i) {
        const float4 xa = (i == 0) ? x0 : px[(size_t)i * F4];
        const float4 xb = px[(size_t)(i + CHUNK) * F4];
        ma = ema4(ma, xa);
        mb = ema4(mb, xb);
    }

    g_local[(size_t)(b * NCHUNK + c)     * F4 + lane] = ma;
    g_local[(size_t)(b * NCHUNK + c + 1) * F4 + lane] = mb;
}

// ---- P3: checkpoint reconstruction + output sweep ----
// grid: NPAIR/4 = 2560 blocks x 128 threads; block = chunks [c0, c0+4) of b.
__global__ void __launch_bounds__(128)
pcen_out(const float4* __restrict__ x4, float4* __restrict__ out4) {
    __shared__ float4 sp[NWIN * F4];    // partial window [klo .. c0+4)

    const int p0   = blockIdx.x * 4;
    const int b    = p0 / NCHUNK;
    const int c0   = p0 % NCHUNK;
    const int w    = threadIdx.x >> 5;
    const int l    = threadIdx.x & 31;
    const int c    = c0 + w;

    const int klo  = (c0 > KT) ? (c0 - KT) : 0;
    const int nwin = (c0 + 3) - klo;          // staged slots (own chunk's
                                              // predecessor set), <= NWIN

    // Cooperative stage of the window (contiguous in g_local).
    const float4* gw = &g_local[(size_t)(b * NCHUNK + klo) * F4];
    for (int i = threadIdx.x; i < nwin * F4; i += 128) {
        sp[i] = gw[i];
    }
    __syncthreads();

    const float aL = a_pow_chunk();

    // Reconstruct checkpoint S(c-1) = state after chunk c-1.
    float4 m;
    const size_t base = (size_t)(b * T_LEN + c * CHUNK) * F4 + l;
    const float4* px = x4 + base;

    if (c == 0) {
        // Pre-state x[0]: a*x0 + s*x0 == x0, uniform update is exact.
        m = px[0];
    } else if (klo > 0) {
        // Fixed window: exactly KT terms, j = w .. w+KT-1 in sp
        // (chunks c-KT .. c-1, oldest first — Horner).
        m = sp[w * F4 + l];
        #pragma unroll 5
        for (int j = w + 1; j < w + KT; ++j) {
            m = comb4(aL, m, sp[j * F4 + l]);
        }
    } else {
        // Near the start: exact combine from chunk 0 (includes true seed).
        m = sp[l];                              // local(0) = true M[CHUNK-1]
        for (int j = 1; j <= c - 1; ++j) {
            m = comb4(aL, m, sp[j * F4 + l]);
        }
    }

    // Output sweep for this chunk.
    float4* po = out4 + base;
    #pragma unroll 5
    for (int i = 0; i < CHUNK; ++i) {
        const float4 xv = px[(size_t)i * F4];
        m = ema4(m, xv);
        float4 o;
        o.x = pcen1(xv.x, m.x);
        o.y = pcen1(xv.y, m.y);
        o.z = pcen1(xv.z, m.z);
        o.w = pcen1(xv.w, m.w);
        __stcs(&po[(size_t)i * F4], o);   // evict-first: keep L2 for x
    }
}

extern "C" void kernel_launch(void* const* d_in, const int* in_sizes, int n_in,
                              void* d_out, int out_size) {
    const float4* x4 = (const float4*)d_in[0];
    float4* out4 = (float4*)d_out;
    (void)in_sizes; (void)n_in; (void)out_size;

    pcen_local<<<NDUO / 4, 128>>>(x4);
    pcen_out  <<<NPAIR / 4, 128>>>(x4, out4);
}